// round 13
// baseline (speedup 1.0000x reference)
#include <cuda_runtime.h>

// CumulantSOAP_CV: per-column mean & variance over X (200000 x 576 fp32),
// then project (cum - mu) @ W -> (1 x 4).
// pass1: byte-identical to R11 best (streaming loop + __ldcs, plain coalesced
//        4-phase partial stores, NO smem epilogue -> 35 regs).
// tail:  148 blocks (one per SM, one wave). Stage A: 4 independent float4
//        loads (one round-trip). PURE busy-wait grid barrier (no __nanosleep
//        -- its wakeup granularity was the suspected 13us floor). Stage B:
//        block 0 folds 148 rows, cumulants, projection, tree-reduce.

#define N_ROWS   200000
#define P        576
#define NBLK     296
#define RPB      ((N_ROWS + NBLK - 1) / NBLK)   // 676 rows per block
#define NPART    (NBLK * 4)                     // 1184 partial rows
#define NRED     148                             // tail blocks (one wave)
#define ROWS_PER_RED (NPART / NRED)              // 8

// Scratch (allocation-free __device__ globals).
__device__ float g_ps [NPART][P];   // partial sums      (2.7 MB)
__device__ float g_pq [NPART][P];   // partial sum-sqs   (2.7 MB)
__device__ float g_ps2[NRED][P];
__device__ float g_pq2[NRED][P];
__device__ int   g_cnt;             // zero-init; reset by block 0 each run

// ---------------------------------------------------------------------------
// Pass 1: streaming reduction over X. blockDim = 576, grid = 296 (2 CTA/SM).
// BYTE-IDENTICAL to R11 (best measured: 80.4us total).
// ---------------------------------------------------------------------------
__global__ __launch_bounds__(576) void pass1_kernel(const float* __restrict__ X) {
    const int b  = blockIdx.x;
    const int t  = threadIdx.x;
    const int c4 = t % 144;      // float4 column index (0..143)
    const int rs = t / 144;      // 0..3

    const int r0 = b * RPB;
    int r1 = r0 + RPB;
    if (r1 > N_ROWS) r1 = N_ROWS;

    const float4* __restrict__ Xv = reinterpret_cast<const float4*>(X);

    float4 s = make_float4(0.f, 0.f, 0.f, 0.f);
    float4 q = make_float4(0.f, 0.f, 0.f, 0.f);

    #pragma unroll 4
    for (int r = r0 + rs; r < r1; r += 4) {
        float4 x = __ldcs(&Xv[(size_t)r * 144 + c4]);
        s.x += x.x; s.y += x.y; s.z += x.z; s.w += x.w;
        q.x += x.x * x.x; q.y += x.y * x.y; q.z += x.z * x.z; q.w += x.w * x.w;
    }

    const int p = b * 4 + rs;
    reinterpret_cast<float4*>(&g_ps[p][0])[c4] = s;
    reinterpret_cast<float4*>(&g_pq[p][0])[c4] = q;
}

// ---------------------------------------------------------------------------
// Tail kernel: 148 blocks x 576 threads. Thread layout (c4 = t%144, rs = t/144).
//  Stage A: block b covers rows [8b, 8b+8); phase rs takes rows 8b+rs and
//           8b+rs+4 -> 4 INDEPENDENT float4 loads (one memory round-trip).
//           Phase-fold via smem, coalesced float4 store to g_ps2/g_pq2.
//  Grid barrier over 148 co-resident blocks: pure busy-wait volatile spin
//           (NO __nanosleep -- its wakeup granularity set a ~13us floor).
//  Stage B: block 0 folds the 148 rows of g_ps2/g_pq2 (phase-split), then
//           cumulants + projection + deterministic tree reduction.
// mom1 == 0 analytically (reference's fp32 residual ~1e-7 is negligible at
// the 1e-3 output tolerance).
// ---------------------------------------------------------------------------
__global__ __launch_bounds__(576) void tail_kernel(const float* __restrict__ mu,
                                                   const float* __restrict__ W,
                                                   float* __restrict__ out) {
    const int b  = blockIdx.x;    // 0..147
    const int t  = threadIdx.x;   // 0..575
    const int c4 = t % 144;
    const int rs = t / 144;       // 0..3

    __shared__ float4 park_s[3][144];
    __shared__ float4 park_q[3][144];

    // ---------------- Stage A: one round-trip fold of 8 rows --------------
    {
        const int i0 = b * ROWS_PER_RED + rs;
        float4 s0 = reinterpret_cast<const float4*>(&g_ps[i0    ][0])[c4];
        float4 s1 = reinterpret_cast<const float4*>(&g_ps[i0 + 4][0])[c4];
        float4 q0 = reinterpret_cast<const float4*>(&g_pq[i0    ][0])[c4];
        float4 q1 = reinterpret_cast<const float4*>(&g_pq[i0 + 4][0])[c4];

        float4 s = make_float4(s0.x + s1.x, s0.y + s1.y, s0.z + s1.z, s0.w + s1.w);
        float4 q = make_float4(q0.x + q1.x, q0.y + q1.y, q0.z + q1.z, q0.w + q1.w);

        if (rs > 0) { park_s[rs - 1][c4] = s; park_q[rs - 1][c4] = q; }
        __syncthreads();
        if (rs == 0) {
            #pragma unroll
            for (int ph = 0; ph < 3; ph++) {
                float4 a = park_s[ph][c4];
                s.x += a.x; s.y += a.y; s.z += a.z; s.w += a.w;
                float4 e = park_q[ph][c4];
                q.x += e.x; q.y += e.y; q.z += e.z; q.w += e.w;
            }
            reinterpret_cast<float4*>(&g_ps2[b][0])[c4] = s;
            reinterpret_cast<float4*>(&g_pq2[b][0])[c4] = q;
        }
    }

    // ---------------- Grid barrier over 148 blocks (busy-wait) ------------
    __threadfence();
    __syncthreads();
    if (t == 0) atomicAdd(&g_cnt, 1);

    if (b != 0) return;

    if (t == 0) {
        while (*(volatile int*)&g_cnt < NRED) { }   // pure spin, 1 thread
        __threadfence();              // acquire: all g_ps2/g_pq2 visible
    }
    __syncthreads();

    // ---------------- Stage B: fold 148 rows (float4, phase-split) --------
    float4 s = make_float4(0.f, 0.f, 0.f, 0.f);
    float4 q = make_float4(0.f, 0.f, 0.f, 0.f);
    #pragma unroll 4
    for (int i = rs; i < NRED; i += 4) {
        float4 a = reinterpret_cast<const float4*>(&g_ps2[i][0])[c4];
        s.x += a.x; s.y += a.y; s.z += a.z; s.w += a.w;
        float4 e = reinterpret_cast<const float4*>(&g_pq2[i][0])[c4];
        q.x += e.x; q.y += e.y; q.z += e.z; q.w += e.w;
    }
    if (rs > 0) { park_s[rs - 1][c4] = s; park_q[rs - 1][c4] = q; }
    __syncthreads();

    __shared__ float4 tot_s[144];
    __shared__ float4 tot_q[144];
    if (rs == 0) {
        #pragma unroll
        for (int ph = 0; ph < 3; ph++) {
            float4 a = park_s[ph][c4];
            s.x += a.x; s.y += a.y; s.z += a.z; s.w += a.w;
            float4 e = park_q[ph][c4];
            q.x += e.x; q.y += e.y; q.z += e.z; q.w += e.w;
        }
        tot_s[c4] = s;
        tot_q[c4] = q;
    }
    __syncthreads();

    // ---------------- Cumulants + projection (thread t = column t) --------
    const float s2 = reinterpret_cast<const float*>(tot_s)[t];
    const float q2 = reinterpret_cast<const float*>(tot_q)[t];

    const float invN = 1.0f / (float)N_ROWS;
    const float m    = s2 * invN;
    const float mom2 = q2 * invN - m * m;

    const int j0 = 3 * t;
    const float d0 = m    - mu[j0 + 0];
    const float d1 = 0.f  - mu[j0 + 1];
    const float d2 = mom2 - mu[j0 + 2];

    float4 acc;
    acc.x = d0 * W[(j0 + 0) * 4 + 0] + d1 * W[(j0 + 1) * 4 + 0] + d2 * W[(j0 + 2) * 4 + 0];
    acc.y = d0 * W[(j0 + 0) * 4 + 1] + d1 * W[(j0 + 1) * 4 + 1] + d2 * W[(j0 + 2) * 4 + 1];
    acc.z = d0 * W[(j0 + 0) * 4 + 2] + d1 * W[(j0 + 1) * 4 + 2] + d2 * W[(j0 + 2) * 4 + 2];
    acc.w = d0 * W[(j0 + 0) * 4 + 3] + d1 * W[(j0 + 1) * 4 + 3] + d2 * W[(j0 + 2) * 4 + 3];

    __shared__ float4 sh3[576];
    sh3[t] = acc;
    __syncthreads();

    if (t < 64) {
        float4 a = sh3[t];
        for (int i = t + 64; i < 576; i += 64) {
            float4 bb = sh3[i];
            a.x += bb.x; a.y += bb.y; a.z += bb.z; a.w += bb.w;
        }
        sh3[t] = a;
    }
    __syncthreads();
    #pragma unroll
    for (int w = 32; w > 0; w >>= 1) {
        if (t < w) {
            float4 a = sh3[t], bb = sh3[t + w];
            a.x += bb.x; a.y += bb.y; a.z += bb.z; a.w += bb.w;
            sh3[t] = a;
        }
        __syncthreads();
    }

    if (t == 0) {
        out[0] = sh3[0].x;
        out[1] = sh3[0].y;
        out[2] = sh3[0].z;
        out[3] = sh3[0].w;
        g_cnt = 0;   // reset for next graph replay (all other blocks done)
    }
}

extern "C" void kernel_launch(void* const* d_in, const int* in_sizes, int n_in,
                              void* d_out, int out_size) {
    (void)in_sizes; (void)n_in; (void)out_size;
    const float* X  = (const float*)d_in[0];   // (200000, 576)
    const float* mu = (const float*)d_in[1];   // (1728,)
    const float* W  = (const float*)d_in[2];   // (1728, 4)
    float* out = (float*)d_out;                // (1, 4)

    pass1_kernel<<<NBLK, 576>>>(X);
    tail_kernel<<<NRED, 576>>>(mu, W, out);
}